// round 5
// baseline (speedup 1.0000x reference)
#include <cuda_runtime.h>

// Problem constants (fixed shapes from reference)
#define BB 16
#define HH 512
#define WW 512
#define H2 1024
#define W2 1024
#define WV (W2 / 4)   // float4 vectors per output row = 256

// Fused: bilinear 2x upsample of mask (2ch) -> x_mask,y_mask;
// fused_c = xm*xl_c + ym*yl_c; out_o = relu(sum_i w[o,i]*fused_i + b_o).
// R5: block = one (batch, input-row) pair covering the full width.
// Mask rows {k-1, k, k+1} x 2 channels loaded cooperatively into smem
// (3 x LDG.128 per thread), taps served from smem. Per thread: 2 output
// rows x 4 cols, 12 float4 stream loads, 10 float4 stores (as in R3).
__global__ void __launch_bounds__(256) fused_upsample_blend_conv_kernel(
    const float* __restrict__ mask,   // (B,2,H,W)
    const float* __restrict__ xl,     // (B,3,H2,W2)
    const float* __restrict__ yl,     // (B,3,H2,W2)
    const float* __restrict__ cw,     // (3,3) row-major 'oi'
    const float* __restrict__ cb,     // (3,)
    float* __restrict__ out)          // (B,3,H2,W2) ++ (B,1,H2,W2) ++ (B,1,H2,W2)
{
    __shared__ float s_mask[6][WW];   // [ch*3 + rowsel][col], 12 KB

    const int tid = threadIdx.x;      // 0..255 = ox4
    const int k   = blockIdx.x & (HH - 1);
    const int b   = blockIdx.x >> 9;  // HH = 512

    int km1 = k - 1; if (km1 < 0) km1 = 0;
    int kp1 = k + 1; if (kp1 > HH - 1) kp1 = HH - 1;
    const int grow[3] = { km1, k, kp1 };

    // ---- cooperative mask load: 6 rows x 128 float4 = 768 float4, 3/thread ----
    const size_t mplane = (size_t)HH * WW;
    #pragma unroll
    for (int i = 0; i < 3; i++) {
        int li   = tid + i * 256;          // 0..767
        int row6 = li >> 7;                // 0..5
        int v4   = li & 127;               // float4 index within row
        int ch   = row6 >= 3;
        int rs   = row6 - 3 * ch;          // 0..2
        const float* src = mask + ((size_t)b * 2 + ch) * mplane
                         + (size_t)grow[rs] * WW + (size_t)v4 * 4;
        float4 v = *(const float4*)src;
        *(float4*)&s_mask[row6][v4 * 4] = v;
    }
    __syncthreads();

    // ---- horizontal taps from smem: cols {m-1, m, m+1, m+2}, clamped ----
    const int m   = tid * 2;               // 0..510, even
    int cm1 = m - 1; if (cm1 < 0) cm1 = 0;
    const int cp1 = m + 1;
    int cp2 = m + 2; if (cp2 > WW - 1) cp2 = WW - 1;

    float xA0 = s_mask[0][cm1], xA1 = s_mask[0][m], xA2 = s_mask[0][cp1], xA3 = s_mask[0][cp2];
    float xB0 = s_mask[1][cm1], xB1 = s_mask[1][m], xB2 = s_mask[1][cp1], xB3 = s_mask[1][cp2];
    float xC0 = s_mask[2][cm1], xC1 = s_mask[2][m], xC2 = s_mask[2][cp1], xC3 = s_mask[2][cp2];
    float yA0 = s_mask[3][cm1], yA1 = s_mask[3][m], yA2 = s_mask[3][cp1], yA3 = s_mask[3][cp2];
    float yB0 = s_mask[4][cm1], yB1 = s_mask[4][m], yB2 = s_mask[4][cp1], yB3 = s_mask[4][cp2];
    float yC0 = s_mask[5][cm1], yC1 = s_mask[5][m], yC2 = s_mask[5][cp1], yC3 = s_mask[5][cp2];

    // vertical interpolation per input column, for even (e) and odd (o) rows
    float vxe0 = 0.25f*xA0 + 0.75f*xB0, vxe1 = 0.25f*xA1 + 0.75f*xB1;
    float vxe2 = 0.25f*xA2 + 0.75f*xB2, vxe3 = 0.25f*xA3 + 0.75f*xB3;
    float vxo0 = 0.75f*xB0 + 0.25f*xC0, vxo1 = 0.75f*xB1 + 0.25f*xC1;
    float vxo2 = 0.75f*xB2 + 0.25f*xC2, vxo3 = 0.75f*xB3 + 0.25f*xC3;
    float vye0 = 0.25f*yA0 + 0.75f*yB0, vye1 = 0.25f*yA1 + 0.75f*yB1;
    float vye2 = 0.25f*yA2 + 0.75f*yB2, vye3 = 0.25f*yA3 + 0.75f*yB3;
    float vyo0 = 0.75f*yB0 + 0.25f*yC0, vyo1 = 0.75f*yB1 + 0.25f*yC1;
    float vyo2 = 0.75f*yB2 + 0.25f*yC2, vyo3 = 0.75f*yB3 + 0.25f*yC3;

    // horizontal combine -> per-row 4-wide masks
    float xme[4], xmo[4], yme[4], ymo[4];
    xme[0] = 0.25f*vxe0 + 0.75f*vxe1;  xme[1] = 0.75f*vxe1 + 0.25f*vxe2;
    xme[2] = 0.25f*vxe1 + 0.75f*vxe2;  xme[3] = 0.75f*vxe2 + 0.25f*vxe3;
    xmo[0] = 0.25f*vxo0 + 0.75f*vxo1;  xmo[1] = 0.75f*vxo1 + 0.25f*vxo2;
    xmo[2] = 0.25f*vxo1 + 0.75f*vxo2;  xmo[3] = 0.75f*vxo2 + 0.25f*vxo3;
    yme[0] = 0.25f*vye0 + 0.75f*vye1;  yme[1] = 0.75f*vye1 + 0.25f*vye2;
    yme[2] = 0.25f*vye1 + 0.75f*vye2;  yme[3] = 0.75f*vye2 + 0.25f*vye3;
    ymo[0] = 0.25f*vyo0 + 0.75f*vyo1;  ymo[1] = 0.75f*vyo1 + 0.25f*vyo2;
    ymo[2] = 0.25f*vyo1 + 0.75f*vyo2;  ymo[3] = 0.75f*vyo2 + 0.25f*vyo3;

    // ---- load xl/yl: 2 rows x 3 channels x 2 tensors = 12 float4 ----
    const size_t plane = (size_t)H2 * W2;
    const int oy0 = 2 * k;
    const size_t base0 = (size_t)b * 3 * plane + (size_t)oy0 * W2 + (size_t)tid * 4;
    const size_t base1 = base0 + W2;   // odd row

    float4 xe0 = *(const float4*)(xl + base0);
    float4 xe1 = *(const float4*)(xl + base0 + plane);
    float4 xe2 = *(const float4*)(xl + base0 + 2 * plane);
    float4 xo0 = *(const float4*)(xl + base1);
    float4 xo1 = *(const float4*)(xl + base1 + plane);
    float4 xo2 = *(const float4*)(xl + base1 + 2 * plane);
    float4 ye0 = *(const float4*)(yl + base0);
    float4 ye1 = *(const float4*)(yl + base0 + plane);
    float4 ye2 = *(const float4*)(yl + base0 + 2 * plane);
    float4 yo0 = *(const float4*)(yl + base1);
    float4 yo1 = *(const float4*)(yl + base1 + plane);
    float4 yo2 = *(const float4*)(yl + base1 + 2 * plane);

    // conv weights / bias
    float w00 = __ldg(cw + 0), w01 = __ldg(cw + 1), w02 = __ldg(cw + 2);
    float w10 = __ldg(cw + 3), w11 = __ldg(cw + 4), w12 = __ldg(cw + 5);
    float w20 = __ldg(cw + 6), w21 = __ldg(cw + 7), w22 = __ldg(cw + 8);
    float b0 = __ldg(cb + 0), b1 = __ldg(cb + 1), b2 = __ldg(cb + 2);

    float* out_main = out;                                   // (B,3,H2,W2)
    float* out_xm   = out + (size_t)BB * 3 * plane;          // (B,1,H2,W2)
    float* out_ym   = out_xm + (size_t)BB * plane;           // (B,1,H2,W2)

    // ---- per-row: blend, channel-mix, relu, store ----
    #pragma unroll
    for (int r = 0; r < 2; r++) {
        const float* xm = r ? xmo : xme;
        const float* ym = r ? ymo : yme;
        float4 c0 = r ? xo0 : xe0, c1 = r ? xo1 : xe1, c2 = r ? xo2 : xe2;
        float4 d0 = r ? yo0 : ye0, d1 = r ? yo1 : ye1, d2 = r ? yo2 : ye2;
        size_t base = r ? base1 : base0;

        float f0[4] = { xm[0]*c0.x + ym[0]*d0.x, xm[1]*c0.y + ym[1]*d0.y,
                        xm[2]*c0.z + ym[2]*d0.z, xm[3]*c0.w + ym[3]*d0.w };
        float f1[4] = { xm[0]*c1.x + ym[0]*d1.x, xm[1]*c1.y + ym[1]*d1.y,
                        xm[2]*c1.z + ym[2]*d1.z, xm[3]*c1.w + ym[3]*d1.w };
        float f2[4] = { xm[0]*c2.x + ym[0]*d2.x, xm[1]*c2.y + ym[1]*d2.y,
                        xm[2]*c2.z + ym[2]*d2.z, xm[3]*c2.w + ym[3]*d2.w };

        float4 o0, o1, o2;
        {
            float rr[4];
            #pragma unroll
            for (int j = 0; j < 4; j++) {
                float v = w00 * f0[j] + w01 * f1[j] + w02 * f2[j] + b0;
                rr[j] = v > 0.0f ? v : 0.0f;
            }
            o0 = make_float4(rr[0], rr[1], rr[2], rr[3]);
            #pragma unroll
            for (int j = 0; j < 4; j++) {
                float v = w10 * f0[j] + w11 * f1[j] + w12 * f2[j] + b1;
                rr[j] = v > 0.0f ? v : 0.0f;
            }
            o1 = make_float4(rr[0], rr[1], rr[2], rr[3]);
            #pragma unroll
            for (int j = 0; j < 4; j++) {
                float v = w20 * f0[j] + w21 * f1[j] + w22 * f2[j] + b2;
                rr[j] = v > 0.0f ? v : 0.0f;
            }
            o2 = make_float4(rr[0], rr[1], rr[2], rr[3]);
        }

        *(float4*)(out_main + base)             = o0;
        *(float4*)(out_main + base + plane)     = o1;
        *(float4*)(out_main + base + 2 * plane) = o2;

        size_t mbase = (size_t)b * plane + (size_t)(oy0 + r) * W2 + (size_t)tid * 4;
        *(float4*)(out_xm + mbase) = make_float4(xm[0], xm[1], xm[2], xm[3]);
        *(float4*)(out_ym + mbase) = make_float4(ym[0], ym[1], ym[2], ym[3]);
    }
}

extern "C" void kernel_launch(void* const* d_in, const int* in_sizes, int n_in,
                              void* d_out, int out_size) {
    const float* mask = (const float*)d_in[0];
    const float* xl   = (const float*)d_in[1];
    const float* yl   = (const float*)d_in[2];
    const float* cw   = (const float*)d_in[3];
    const float* cb   = (const float*)d_in[4];
    float* out = (float*)d_out;

    const int blocks = BB * HH;              // 8192 blocks, one per (b, row-pair)
    fused_upsample_blend_conv_kernel<<<blocks, 256>>>(mask, xl, yl, cw, cb, out);
}

// round 7
// speedup vs baseline: 1.0547x; 1.0547x over previous
#include <cuda_runtime.h>

// Problem constants (fixed shapes from reference)
#define BB 16
#define HH 512
#define WW 512
#define H2 1024
#define W2 1024
#define WV (W2 / 4)    // float4 vectors per output row = 256
#define HT (HH / 2)    // 4-row tiles per batch = 256

// Fused: bilinear 2x upsample of mask (2ch) -> x_mask,y_mask;
// fused_c = xm*xl_c + ym*yl_c; out_o = relu(sum_i w[o,i]*fused_i + b_o).
// R6: one thread = 4 consecutive output rows (4j..4j+3) x 4 columns.
// Mask rows {kb-1..kb+2} shared across the 4 output rows; stream accesses
// keep R3's 16B-thread-stride (4 full lines per warp LDG.128).
__global__ void __launch_bounds__(256) fused_upsample_blend_conv_kernel(
    const float* __restrict__ mask,   // (B,2,H,W)
    const float* __restrict__ xl,     // (B,3,H2,W2)
    const float* __restrict__ yl,     // (B,3,H2,W2)
    const float* __restrict__ cw,     // (3,3) row-major 'oi'
    const float* __restrict__ cb,     // (3,)
    float* __restrict__ out)          // (B,3,H2,W2) ++ (B,1,H2,W2) ++ (B,1,H2,W2)
{
    int idx = blockIdx.x * blockDim.x + threadIdx.x;
    int ox4 = idx & (WV - 1);        // vector index along width
    int t   = idx >> 8;              // WV = 256
    int j   = t & (HT - 1);          // 4-row tile index
    int b   = t >> 8;                // HT = 256
    if (b >= BB) return;

    const int kb = 2 * j;            // input base row (even): rows kb-1..kb+2
    int rA = kb - 1; if (rA < 0) rA = 0;
    const int rB = kb;
    const int rC = kb + 1;                       // <= 511 always
    int rD = kb + 2; if (rD > HH - 1) rD = HH - 1;

    // ---- horizontal: 4 outputs share input cols {m-1, m, m+1, m+2} ----
    int m   = ox4 * 2;                       // 0..510, even
    int cm1 = m - 1; if (cm1 < 0) cm1 = 0;
    int cp1 = m + 1;                         // <= 511 always
    int cp2 = m + 2; if (cp2 > WW - 1) cp2 = WW - 1;

    const size_t mplane = (size_t)HH * WW;
    const float* mx = mask + ((size_t)b * 2 + 0) * mplane;
    const float* my = mask + ((size_t)b * 2 + 1) * mplane;

    // raw mask samples: 4 rows x 4 cols x 2 channels = 32 scalars
    const float* pxA = mx + (size_t)rA * WW;  const float* pxB = mx + (size_t)rB * WW;
    const float* pxC = mx + (size_t)rC * WW;  const float* pxD = mx + (size_t)rD * WW;
    const float* pyA = my + (size_t)rA * WW;  const float* pyB = my + (size_t)rB * WW;
    const float* pyC = my + (size_t)rC * WW;  const float* pyD = my + (size_t)rD * WW;

    float xA0=__ldg(pxA+cm1), xA1=__ldg(pxA+m), xA2=__ldg(pxA+cp1), xA3=__ldg(pxA+cp2);
    float xB0=__ldg(pxB+cm1), xB1=__ldg(pxB+m), xB2=__ldg(pxB+cp1), xB3=__ldg(pxB+cp2);
    float xC0=__ldg(pxC+cm1), xC1=__ldg(pxC+m), xC2=__ldg(pxC+cp1), xC3=__ldg(pxC+cp2);
    float xD0=__ldg(pxD+cm1), xD1=__ldg(pxD+m), xD2=__ldg(pxD+cp1), xD3=__ldg(pxD+cp2);
    float yA0=__ldg(pyA+cm1), yA1=__ldg(pyA+m), yA2=__ldg(pyA+cp1), yA3=__ldg(pyA+cp2);
    float yB0=__ldg(pyB+cm1), yB1=__ldg(pyB+m), yB2=__ldg(pyB+cp1), yB3=__ldg(pyB+cp2);
    float yC0=__ldg(pyC+cm1), yC1=__ldg(pyC+m), yC2=__ldg(pyC+cp1), yC3=__ldg(pyC+cp2);
    float yD0=__ldg(pyD+cm1), yD1=__ldg(pyD+m), yD2=__ldg(pyD+cp1), yD3=__ldg(pyD+cp2);

    // vertical interpolation per input column: 4 output rows
    // r0 (even, in-row kb):   0.25*A + 0.75*B
    // r1 (odd,  in-row kb):   0.75*B + 0.25*C
    // r2 (even, in-row kb+1): 0.25*B + 0.75*C
    // r3 (odd,  in-row kb+1): 0.75*C + 0.25*D
    float vx[4][4], vy[4][4];
    vx[0][0]=0.25f*xA0+0.75f*xB0; vx[0][1]=0.25f*xA1+0.75f*xB1; vx[0][2]=0.25f*xA2+0.75f*xB2; vx[0][3]=0.25f*xA3+0.75f*xB3;
    vx[1][0]=0.75f*xB0+0.25f*xC0; vx[1][1]=0.75f*xB1+0.25f*xC1; vx[1][2]=0.75f*xB2+0.25f*xC2; vx[1][3]=0.75f*xB3+0.25f*xC3;
    vx[2][0]=0.25f*xB0+0.75f*xC0; vx[2][1]=0.25f*xB1+0.75f*xC1; vx[2][2]=0.25f*xB2+0.75f*xC2; vx[2][3]=0.25f*xB3+0.75f*xC3;
    vx[3][0]=0.75f*xC0+0.25f*xD0; vx[3][1]=0.75f*xC1+0.25f*xD1; vx[3][2]=0.75f*xC2+0.25f*xD2; vx[3][3]=0.75f*xC3+0.25f*xD3;
    vy[0][0]=0.25f*yA0+0.75f*yB0; vy[0][1]=0.25f*yA1+0.75f*yB1; vy[0][2]=0.25f*yA2+0.75f*yB2; vy[0][3]=0.25f*yA3+0.75f*yB3;
    vy[1][0]=0.75f*yB0+0.25f*yC0; vy[1][1]=0.75f*yB1+0.25f*yC1; vy[1][2]=0.75f*yB2+0.25f*yC2; vy[1][3]=0.75f*yB3+0.25f*yC3;
    vy[2][0]=0.25f*yB0+0.75f*yC0; vy[2][1]=0.25f*yB1+0.75f*yC1; vy[2][2]=0.25f*yB2+0.75f*yC2; vy[2][3]=0.25f*yB3+0.75f*yC3;
    vy[3][0]=0.75f*yC0+0.25f*yD0; vy[3][1]=0.75f*yC1+0.25f*yD1; vy[3][2]=0.75f*yC2+0.25f*yD2; vy[3][3]=0.75f*yC3+0.25f*yD3;

    // horizontal combine -> per-row 4-wide masks
    float xm[4][4], ym[4][4];
    #pragma unroll
    for (int r = 0; r < 4; r++) {
        xm[r][0] = 0.25f*vx[r][0] + 0.75f*vx[r][1];
        xm[r][1] = 0.75f*vx[r][1] + 0.25f*vx[r][2];
        xm[r][2] = 0.25f*vx[r][1] + 0.75f*vx[r][2];
        xm[r][3] = 0.75f*vx[r][2] + 0.25f*vx[r][3];
        ym[r][0] = 0.25f*vy[r][0] + 0.75f*vy[r][1];
        ym[r][1] = 0.75f*vy[r][1] + 0.25f*vy[r][2];
        ym[r][2] = 0.25f*vy[r][1] + 0.75f*vy[r][2];
        ym[r][3] = 0.75f*vy[r][2] + 0.25f*vy[r][3];
    }

    // conv weights / bias
    float w00 = __ldg(cw + 0), w01 = __ldg(cw + 1), w02 = __ldg(cw + 2);
    float w10 = __ldg(cw + 3), w11 = __ldg(cw + 4), w12 = __ldg(cw + 5);
    float w20 = __ldg(cw + 6), w21 = __ldg(cw + 7), w22 = __ldg(cw + 8);
    float b0 = __ldg(cb + 0), b1 = __ldg(cb + 1), b2 = __ldg(cb + 2);

    const size_t plane = (size_t)H2 * W2;
    const int oy0 = 4 * j;
    const size_t base0 = (size_t)b * 3 * plane + (size_t)oy0 * W2 + (size_t)ox4 * 4;

    float* out_main = out;                                   // (B,3,H2,W2)
    float* out_xm   = out + (size_t)BB * 3 * plane;          // (B,1,H2,W2)
    float* out_ym   = out_xm + (size_t)BB * plane;           // (B,1,H2,W2)

    // ---- per output row: stream loads, blend, channel-mix, relu, store ----
    #pragma unroll
    for (int r = 0; r < 4; r++) {
        const size_t base = base0 + (size_t)r * W2;

        float4 c0 = *(const float4*)(xl + base);
        float4 c1 = *(const float4*)(xl + base + plane);
        float4 c2 = *(const float4*)(xl + base + 2 * plane);
        float4 d0 = *(const float4*)(yl + base);
        float4 d1 = *(const float4*)(yl + base + plane);
        float4 d2 = *(const float4*)(yl + base + 2 * plane);

        float f0[4] = { xm[r][0]*c0.x + ym[r][0]*d0.x, xm[r][1]*c0.y + ym[r][1]*d0.y,
                        xm[r][2]*c0.z + ym[r][2]*d0.z, xm[r][3]*c0.w + ym[r][3]*d0.w };
        float f1[4] = { xm[r][0]*c1.x + ym[r][0]*d1.x, xm[r][1]*c1.y + ym[r][1]*d1.y,
                        xm[r][2]*c1.z + ym[r][2]*d1.z, xm[r][3]*c1.w + ym[r][3]*d1.w };
        float f2[4] = { xm[r][0]*c2.x + ym[r][0]*d2.x, xm[r][1]*c2.y + ym[r][1]*d2.y,
                        xm[r][2]*c2.z + ym[r][2]*d2.z, xm[r][3]*c2.w + ym[r][3]*d2.w };

        float4 o0, o1, o2;
        {
            float rr[4];
            #pragma unroll
            for (int q = 0; q < 4; q++) {
                float v = w00 * f0[q] + w01 * f1[q] + w02 * f2[q] + b0;
                rr[q] = v > 0.0f ? v : 0.0f;
            }
            o0 = make_float4(rr[0], rr[1], rr[2], rr[3]);
            #pragma unroll
            for (int q = 0; q < 4; q++) {
                float v = w10 * f0[q] + w11 * f1[q] + w12 * f2[q] + b1;
                rr[q] = v > 0.0f ? v : 0.0f;
            }
            o1 = make_float4(rr[0], rr[1], rr[2], rr[3]);
            #pragma unroll
            for (int q = 0; q < 4; q++) {
                float v = w20 * f0[q] + w21 * f1[q] + w22 * f2[q] + b2;
                rr[q] = v > 0.0f ? v : 0.0f;
            }
            o2 = make_float4(rr[0], rr[1], rr[2], rr[3]);
        }

        *(float4*)(out_main + base)             = o0;
        *(float4*)(out_main + base + plane)     = o1;
        *(float4*)(out_main + base + 2 * plane) = o2;

        size_t mbase = (size_t)b * plane + (size_t)(oy0 + r) * W2 + (size_t)ox4 * 4;
        *(float4*)(out_xm + mbase) = make_float4(xm[r][0], xm[r][1], xm[r][2], xm[r][3]);
        *(float4*)(out_ym + mbase) = make_float4(ym[r][0], ym[r][1], ym[r][2], ym[r][3]);
    }
}

extern "C" void kernel_launch(void* const* d_in, const int* in_sizes, int n_in,
                              void* d_out, int out_size) {
    const float* mask = (const float*)d_in[0];
    const float* xl   = (const float*)d_in[1];
    const float* yl   = (const float*)d_in[2];
    const float* cw   = (const float*)d_in[3];
    const float* cb   = (const float*)d_in[4];
    float* out = (float*)d_out;

    const int total = BB * HT * WV;          // 1,048,576 threads (4 rows each)
    const int threads = 256;
    const int blocks = (total + threads - 1) / threads;
    fused_upsample_blend_conv_kernel<<<blocks, threads>>>(mask, xl, yl, cw, cb, out);
}